// round 15
// baseline (speedup 1.0000x reference)
#include <cuda_runtime.h>
#include <cstdint>

#define K_NEIGH 20
#define THRES 0.5f
#define WPB 8
#define LCAP 16
#define SCAP 128
#define PIVOT 0.012f

// One warp per row of the (B*N, N) fp32 distance matrix. Output dtype f32.
//
// Ordering: ascending (value bits, index) == jax.lax.top_k(-x, 20) stable
// output order (x >= 0 so float bits are monotone in value).
//
// Fast path:
//   1) screened filter (R10-proven): 4 independent LDG.128/lane, FMIN tree,
//      inspect only 16-elem groups containing a value < PIVOT
//   2) warp-scan compaction into split shared arrays (bits[], idx[])
//   3) rank selection with 32-bit compares (LDS.32+ISETP+IADD inner loop);
//      exactness guard: warp-reduced Sum(rank) == C(C-1)/2 iff all bits
//      distinct — any duplicate lowers the sum -> exact fallback.
// Fallback (exact, any input): 20 rounds of bounded u64 warp-min over the
// full row — on lane overflow, C < 20, C > SCAP, or duplicate value bits.
//
// __launch_bounds__(256, 8): hard-cap 32 regs/thread -> 8 blocks/SM. R11/R14
// both proved occupancy (not per-warp ILP) is what feeds DRAM here.

__device__ __forceinline__ unsigned long long warp_min_u64(unsigned long long m) {
    #pragma unroll
    for (int off = 16; off > 0; off >>= 1) {
        unsigned long long o = __shfl_xor_sync(0xFFFFFFFFu, m, off);
        if (o < m) m = o;
    }
    return m;
}

__global__ void __launch_bounds__(WPB * 32, 8)
knn_thres_kernel(const float* __restrict__ x, float* __restrict__ out,
                 int N, int rows) {
    __shared__ unsigned int cb[WPB][SCAP];   // candidate value bits
    __shared__ int          ci[WPB][SCAP];   // candidate indices

    const int warp = threadIdx.x >> 5;
    const int lane = threadIdx.x & 31;
    const int row  = blockIdx.x * WPB + warp;
    if (row >= rows) return;

    const float* __restrict__ xrow = x + (size_t)row * (size_t)N;

    unsigned int lb[LCAP];
    int          li[LCAP];
    int cl = 0;

    const int nvec = N >> 2;
    const float4* __restrict__ xv = (const float4*)xrow;

    auto push4 = [&](float4 v, int vecidx, float mv) {
        if (mv < PIVOT) {
            float vs[4] = {v.x, v.y, v.z, v.w};
            const int base = vecidx << 2;
            #pragma unroll
            for (int j = 0; j < 4; j++) {
                if (vs[j] < PIVOT) {
                    if (cl < LCAP) {
                        lb[cl] = __float_as_uint(vs[j]);
                        li[cl] = base + j;
                    }
                    cl++;
                }
            }
        }
    };

    // ---- Phase 1: screened filter, 4 vectors (16 elems) per check ----
    const int ngroups = nvec >> 7;             // 4 vectors x 32 lanes per group
    for (int g = 0; g < ngroups; g++) {
        const int i = lane + (g << 7);
        float4 a = xv[i];
        float4 b = xv[i + 32];
        float4 c = xv[i + 64];
        float4 d = xv[i + 96];
        float ma = fminf(fminf(a.x, a.y), fminf(a.z, a.w));
        float mb = fminf(fminf(b.x, b.y), fminf(b.z, b.w));
        float mc = fminf(fminf(c.x, c.y), fminf(c.z, c.w));
        float md = fminf(fminf(d.x, d.y), fminf(d.z, d.w));
        if (fminf(fminf(ma, mb), fminf(mc, md)) < PIVOT) {
            push4(a, i, ma);
            push4(b, i + 32, mb);
            push4(c, i + 64, mc);
            push4(d, i + 96, md);
        }
    }
    // remainder vectors (nvec % 128 != 0; not hit for N = 4096)
    for (int i = lane + (ngroups << 7); i < nvec; i += 32) {
        float4 v = xv[i];
        float mv = fminf(fminf(v.x, v.y), fminf(v.z, v.w));
        push4(v, i, mv);
    }
    // scalar tail (N % 4 != 0; not hit for N = 4096)
    for (int i = (nvec << 2) + lane; i < N; i += 32) {
        float v = xrow[i];
        if (v < PIVOT) {
            if (cl < LCAP) { lb[cl] = __float_as_uint(v); li[cl] = i; }
            cl++;
        }
    }

    // ---- warp scan: overflow check, total, exclusive offsets ----
    const unsigned ovf = __ballot_sync(0xFFFFFFFFu, cl > LCAP);
    int incl = cl;
    #pragma unroll
    for (int off = 1; off < 32; off <<= 1) {
        int o = __shfl_up_sync(0xFFFFFFFFu, incl, off);
        if (lane >= off) incl += o;
    }
    const int tot  = __shfl_sync(0xFFFFFFFFu, incl, 31);
    const int offs = incl - cl;
    bool fast = (ovf == 0u) && (tot >= K_NEIGH) && (tot <= SCAP);

    const float self_idx = (float)(row % N);        // row index within batch
    float* __restrict__ orow = out + (size_t)row * K_NEIGH;

    if (fast) {
        // ---- Phase 2: compact into split shared arrays ----
        for (int t = 0; t < cl; t++) {
            cb[warp][offs + t] = lb[t];
            ci[warp][offs + t] = li[t];
        }
        __syncwarp();

        // ---- Phase 3: rank selection (32-bit compares) + exactness guard --
        const int C = tot;
        const unsigned int* __restrict__ wb = cb[warp];
        int ranksum = 0;
        for (int s = lane; s < C; s += 32) {
            const unsigned int kb = wb[s];
            int rank = 0;
            #pragma unroll 4
            for (int j = 0; j < C; j++)
                rank += (wb[j] < kb) ? 1 : 0;
            ranksum += rank;
            if (rank < K_NEIGH) {
                float val = __uint_as_float(kb);
                float idx = (float)ci[warp][s];
                orow[rank] = (val > THRES) ? self_idx : idx;
            }
        }
        // all bits distinct  <=>  Sum(rank) == C*(C-1)/2
        #pragma unroll
        for (int off = 16; off > 0; off >>= 1)
            ranksum += __shfl_xor_sync(0xFFFFFFFFu, ranksum, off);
        if (ranksum != (C * (C - 1)) / 2) fast = false;  // duplicates -> redo
    }

    if (!fast) {
        // ---- Exact fallback: 20 bounded u64 warp-min rounds (any input) ----
        unsigned long long prev = 0ULL;             // keys are (bits+1)<<32|i > 0
        for (int sel = 0; sel < K_NEIGH; sel++) {
            unsigned long long m = ~0ULL;
            for (int i = lane; i < N; i += 32) {
                unsigned int bits = __float_as_uint(xrow[i]) + 1u;
                unsigned long long k =
                    ((unsigned long long)bits << 32) | (unsigned int)i;
                if (k > prev && k < m) m = k;
            }
            m = warp_min_u64(m);
            prev = m;
            if (lane == 0) {
                unsigned int bits = (unsigned int)(m >> 32) - 1u;
                float val = __uint_as_float(bits);
                float idx = (float)(unsigned int)(m & 0xFFFFFFFFu);
                orow[sel] = (val > THRES) ? self_idx : idx;
            }
        }
    }
}

extern "C" void kernel_launch(void* const* d_in, const int* in_sizes, int n_in,
                              void* d_out, int out_size) {
    // the distance matrix is by far the largest input
    int xi = 0;
    for (int i = 1; i < n_in; i++)
        if (in_sizes[i] > in_sizes[xi]) xi = i;

    const float* x = (const float*)d_in[xi];
    float* out = (float*)d_out;

    const int rows = out_size / K_NEIGH;            // B * N  (= 65536 expected)
    const int N    = in_sizes[xi] / rows;           // num points (= 4096 expected)

    const int blocks = (rows + WPB - 1) / WPB;
    knn_thres_kernel<<<blocks, WPB * 32>>>(x, out, N, rows);
}

// round 16
// speedup vs baseline: 1.0419x; 1.0419x over previous
#include <cuda_runtime.h>
#include <cstdint>

#define K_NEIGH 20
#define THRES 0.5f
#define WPB 8
#define LCAP 16
#define SCAP 128
#define PIVOT 0.012f

// One warp per row of the (B*N, N) fp32 distance matrix. Output dtype f32.
//
// Key = ((float_bits(x)+1) << 32) | col : unique; ascending key order ==
// (value asc, col asc) == jax.lax.top_k(-x, 20) stable output order.
//
// Structure == R10 (the 209us / occ 89.6% kernel) with ONE change: the rank
// selection runs on unpacked 32-bit value words (LDS.32+ISETP+IADD inner
// loop) instead of u64 keys, with an exactness guard:
//   warp-reduced Sum(rank) == C(C-1)/2  iff all value words distinct;
//   any duplicate lowers the sum -> exact u64 full-row fallback.
// Fallback also taken on lane overflow, C < 20, or C > SCAP -> correct for
// ANY input. No forced occupancy cap (R15 showed it induces spills); this
// code needs <= 32 regs naturally like R10.

__device__ __forceinline__ unsigned long long warp_min_u64(unsigned long long m) {
    #pragma unroll
    for (int off = 16; off > 0; off >>= 1) {
        unsigned long long o = __shfl_xor_sync(0xFFFFFFFFu, m, off);
        if (o < m) m = o;
    }
    return m;
}

__global__ void __launch_bounds__(WPB * 32)
knn_thres_kernel(const float* __restrict__ x, float* __restrict__ out,
                 int N, int rows) {
    __shared__ unsigned int cb[WPB][SCAP];   // candidate value word (bits+1)
    __shared__ int          ci[WPB][SCAP];   // candidate index

    const int warp = threadIdx.x >> 5;
    const int lane = threadIdx.x & 31;
    const int row  = blockIdx.x * WPB + warp;
    if (row >= rows) return;

    const float* __restrict__ xrow = x + (size_t)row * (size_t)N;

    unsigned long long loc[LCAP];            // same storage as R10
    int cl = 0;

    const int nvec = N >> 2;
    const float4* __restrict__ xv = (const float4*)xrow;

    auto push4 = [&](float4 v, int vecidx, float mv) {
        if (mv < PIVOT) {
            float vs[4] = {v.x, v.y, v.z, v.w};
            const int base = vecidx << 2;
            #pragma unroll
            for (int j = 0; j < 4; j++) {
                if (vs[j] < PIVOT) {
                    if (cl < LCAP) {
                        unsigned int bits = __float_as_uint(vs[j]) + 1u;
                        loc[cl] = ((unsigned long long)bits << 32)
                                  | (unsigned int)(base + j);
                    }
                    cl++;
                }
            }
        }
    };

    // ---- Phase 1 (R10-identical): screened filter, 16 elems per check ----
    const int ngroups = nvec >> 7;             // 4 vectors x 32 lanes per group
    for (int g = 0; g < ngroups; g++) {
        const int i = lane + (g << 7);
        float4 a = xv[i];
        float4 b = xv[i + 32];
        float4 c = xv[i + 64];
        float4 d = xv[i + 96];
        float ma = fminf(fminf(a.x, a.y), fminf(a.z, a.w));
        float mb = fminf(fminf(b.x, b.y), fminf(b.z, b.w));
        float mc = fminf(fminf(c.x, c.y), fminf(c.z, c.w));
        float md = fminf(fminf(d.x, d.y), fminf(d.z, d.w));
        if (fminf(fminf(ma, mb), fminf(mc, md)) < PIVOT) {
            push4(a, i, ma);
            push4(b, i + 32, mb);
            push4(c, i + 64, mc);
            push4(d, i + 96, md);
        }
    }
    // remainder vectors (nvec % 128 != 0; not hit for N = 4096)
    for (int i = lane + (ngroups << 7); i < nvec; i += 32) {
        float4 v = xv[i];
        float mv = fminf(fminf(v.x, v.y), fminf(v.z, v.w));
        push4(v, i, mv);
    }
    // scalar tail (N % 4 != 0; not hit for N = 4096)
    for (int i = (nvec << 2) + lane; i < N; i += 32) {
        float v = xrow[i];
        if (v < PIVOT) {
            if (cl < LCAP) {
                unsigned int bits = __float_as_uint(v) + 1u;
                loc[cl] = ((unsigned long long)bits << 32) | (unsigned int)i;
            }
            cl++;
        }
    }

    // ---- warp scan: overflow check, total, exclusive offsets ----
    const unsigned ovf = __ballot_sync(0xFFFFFFFFu, cl > LCAP);
    int incl = cl;
    #pragma unroll
    for (int off = 1; off < 32; off <<= 1) {
        int o = __shfl_up_sync(0xFFFFFFFFu, incl, off);
        if (lane >= off) incl += o;
    }
    const int tot  = __shfl_sync(0xFFFFFFFFu, incl, 31);
    const int offs = incl - cl;
    bool fast = (ovf == 0u) && (tot >= K_NEIGH) && (tot <= SCAP);

    const float self_idx = (float)(row % N);        // row index within batch
    float* __restrict__ orow = out + (size_t)row * K_NEIGH;

    if (fast) {
        // ---- Phase 2: compact, unpacking u64 -> split 32-bit arrays ----
        for (int t = 0; t < cl; t++) {
            const unsigned long long k = loc[t];
            cb[warp][offs + t] = (unsigned int)(k >> 32);
            ci[warp][offs + t] = (int)(unsigned int)(k & 0xFFFFFFFFu);
        }
        __syncwarp();

        // ---- Phase 3: rank selection (32-bit compares) + exactness guard --
        const int C = tot;
        const unsigned int* __restrict__ wb = cb[warp];
        int ranksum = 0;
        for (int s = lane; s < C; s += 32) {
            const unsigned int kb = wb[s];
            int rank = 0;
            #pragma unroll 4
            for (int j = 0; j < C; j++)
                rank += (wb[j] < kb) ? 1 : 0;
            ranksum += rank;
            if (rank < K_NEIGH) {
                float val = __uint_as_float(kb - 1u);
                float idx = (float)ci[warp][s];
                orow[rank] = (val > THRES) ? self_idx : idx;
            }
        }
        // all value words distinct  <=>  Sum(rank) == C*(C-1)/2
        #pragma unroll
        for (int off = 16; off > 0; off >>= 1)
            ranksum += __shfl_xor_sync(0xFFFFFFFFu, ranksum, off);
        if (ranksum != (C * (C - 1)) / 2) fast = false;  // duplicates -> redo
    }

    if (!fast) {
        // ---- Exact fallback: 20 bounded u64 warp-min rounds (any input) ----
        unsigned long long prev = 0ULL;             // keys are (bits+1)<<32|i > 0
        for (int sel = 0; sel < K_NEIGH; sel++) {
            unsigned long long m = ~0ULL;
            for (int i = lane; i < N; i += 32) {
                unsigned int bits = __float_as_uint(xrow[i]) + 1u;
                unsigned long long k =
                    ((unsigned long long)bits << 32) | (unsigned int)i;
                if (k > prev && k < m) m = k;
            }
            m = warp_min_u64(m);
            prev = m;
            if (lane == 0) {
                unsigned int bits = (unsigned int)(m >> 32) - 1u;
                float val = __uint_as_float(bits);
                float idx = (float)(unsigned int)(m & 0xFFFFFFFFu);
                orow[sel] = (val > THRES) ? self_idx : idx;
            }
        }
    }
}

extern "C" void kernel_launch(void* const* d_in, const int* in_sizes, int n_in,
                              void* d_out, int out_size) {
    // the distance matrix is by far the largest input
    int xi = 0;
    for (int i = 1; i < n_in; i++)
        if (in_sizes[i] > in_sizes[xi]) xi = i;

    const float* x = (const float*)d_in[xi];
    float* out = (float*)d_out;

    const int rows = out_size / K_NEIGH;            // B * N  (= 65536 expected)
    const int N    = in_sizes[xi] / rows;           // num points (= 4096 expected)

    const int blocks = (rows + WPB - 1) / WPB;
    knn_thres_kernel<<<blocks, WPB * 32>>>(x, out, N, rows);
}

// round 17
// speedup vs baseline: 1.2815x; 1.2300x over previous
#include <cuda_runtime.h>
#include <cstdint>

#define K_NEIGH 20
#define THRES 0.5f
#define WPB 8
#define SCAP 128
#define PIVOT 0.012f

// One warp per row of the (B*N, N) fp32 distance matrix. Output dtype f32.
//
// Ordering: ascending (value bits, index) == jax.lax.top_k(-x, 20) stable
// output order (x >= 0 so float bits are monotone in value).
//
// Fast path:
//   1) screened filter (R10-proven shape): 4 independent LDG.128/lane,
//      FMIN tree, inspect only 16-elem groups containing a value < PIVOT.
//      Candidates are pushed DIRECTLY to per-warp shared arrays via shared
//      atomicAdd -- no per-lane local arrays (the R11..R16 register hog).
//   2) rank selection with 32-bit compares (LDS.32+ISETP+IADD inner loop);
//      scatter to out[rank] for rank < 20.
//   3) exactness guard: warp-reduced Sum(rank) == C(C-1)/2 iff all value
//      bits distinct; any duplicate lowers the sum -> exact fallback.
// Fallback (exact, any input): 20 rounds of bounded u64 warp-min over the
// full row -- on C < 20, C > SCAP, or duplicate value bits.
// Output order never depends on shared-buffer fill order (rank-based), so
// the kernel is deterministic.

__device__ __forceinline__ unsigned long long warp_min_u64(unsigned long long m) {
    #pragma unroll
    for (int off = 16; off > 0; off >>= 1) {
        unsigned long long o = __shfl_xor_sync(0xFFFFFFFFu, m, off);
        if (o < m) m = o;
    }
    return m;
}

__global__ void __launch_bounds__(WPB * 32)
knn_thres_kernel(const float* __restrict__ x, float* __restrict__ out,
                 int N, int rows) {
    __shared__ unsigned int cb[WPB][SCAP];   // candidate value bits
    __shared__ int          ci[WPB][SCAP];   // candidate indices
    __shared__ int          cnt[WPB];

    const int warp = threadIdx.x >> 5;
    const int lane = threadIdx.x & 31;
    const int row  = blockIdx.x * WPB + warp;
    if (row >= rows) return;

    const float* __restrict__ xrow = x + (size_t)row * (size_t)N;
    if (lane == 0) cnt[warp] = 0;
    __syncwarp();

    const int nvec = N >> 2;
    const float4* __restrict__ xv = (const float4*)xrow;

    // push all elements of one float4 that pass the pivot (vector pre-screened)
    auto push4 = [&](float4 v, int vecidx, float mv) {
        if (mv < PIVOT) {
            float vs[4] = {v.x, v.y, v.z, v.w};
            const int base = vecidx << 2;
            #pragma unroll
            for (int j = 0; j < 4; j++) {
                if (vs[j] < PIVOT) {
                    int pos = atomicAdd(&cnt[warp], 1);
                    if (pos < SCAP) {
                        cb[warp][pos] = __float_as_uint(vs[j]);
                        ci[warp][pos] = base + j;
                    }
                }
            }
        }
    };

    // ---- Phase 1: screened filter, 4 vectors (16 elems) per check ----
    const int ngroups = nvec >> 7;             // 4 vectors x 32 lanes per group
    for (int g = 0; g < ngroups; g++) {
        const int i = lane + (g << 7);
        float4 a = xv[i];
        float4 b = xv[i + 32];
        float4 c = xv[i + 64];
        float4 d = xv[i + 96];
        float ma = fminf(fminf(a.x, a.y), fminf(a.z, a.w));
        float mb = fminf(fminf(b.x, b.y), fminf(b.z, b.w));
        float mc = fminf(fminf(c.x, c.y), fminf(c.z, c.w));
        float md = fminf(fminf(d.x, d.y), fminf(d.z, d.w));
        if (fminf(fminf(ma, mb), fminf(mc, md)) < PIVOT) {
            push4(a, i, ma);
            push4(b, i + 32, mb);
            push4(c, i + 64, mc);
            push4(d, i + 96, md);
        }
    }
    // remainder vectors (nvec % 128 != 0; not hit for N = 4096)
    for (int i = lane + (ngroups << 7); i < nvec; i += 32) {
        float4 v = xv[i];
        float mv = fminf(fminf(v.x, v.y), fminf(v.z, v.w));
        push4(v, i, mv);
    }
    // scalar tail (N % 4 != 0; not hit for N = 4096)
    for (int i = (nvec << 2) + lane; i < N; i += 32) {
        float v = xrow[i];
        if (v < PIVOT) {
            int pos = atomicAdd(&cnt[warp], 1);
            if (pos < SCAP) {
                cb[warp][pos] = __float_as_uint(v);
                ci[warp][pos] = i;
            }
        }
    }
    __syncwarp();

    const int C = cnt[warp];
    bool fast = (C >= K_NEIGH) && (C <= SCAP);

    const float self_idx = (float)(row % N);        // row index within batch
    float* __restrict__ orow = out + (size_t)row * K_NEIGH;

    if (fast) {
        // ---- Phase 2: rank selection (32-bit compares) + exactness guard --
        const unsigned int* __restrict__ wb = cb[warp];
        int ranksum = 0;
        for (int s = lane; s < C; s += 32) {
            const unsigned int kb = wb[s];
            int rank = 0;
            #pragma unroll 4
            for (int j = 0; j < C; j++)
                rank += (wb[j] < kb) ? 1 : 0;
            ranksum += rank;
            if (rank < K_NEIGH) {
                float val = __uint_as_float(kb);
                float idx = (float)ci[warp][s];
                orow[rank] = (val > THRES) ? self_idx : idx;
            }
        }
        // all value bits distinct  <=>  Sum(rank) == C*(C-1)/2
        #pragma unroll
        for (int off = 16; off > 0; off >>= 1)
            ranksum += __shfl_xor_sync(0xFFFFFFFFu, ranksum, off);
        if (ranksum != (C * (C - 1)) / 2) fast = false;  // duplicates -> redo
    }

    if (!fast) {
        // ---- Exact fallback: 20 bounded u64 warp-min rounds (any input) ----
        unsigned long long prev = 0ULL;             // keys are (bits+1)<<32|i > 0
        for (int sel = 0; sel < K_NEIGH; sel++) {
            unsigned long long m = ~0ULL;
            for (int i = lane; i < N; i += 32) {
                unsigned int bits = __float_as_uint(xrow[i]) + 1u;
                unsigned long long k =
                    ((unsigned long long)bits << 32) | (unsigned int)i;
                if (k > prev && k < m) m = k;
            }
            m = warp_min_u64(m);
            prev = m;
            if (lane == 0) {
                unsigned int bits = (unsigned int)(m >> 32) - 1u;
                float val = __uint_as_float(bits);
                float idx = (float)(unsigned int)(m & 0xFFFFFFFFu);
                orow[sel] = (val > THRES) ? self_idx : idx;
            }
        }
    }
}

extern "C" void kernel_launch(void* const* d_in, const int* in_sizes, int n_in,
                              void* d_out, int out_size) {
    // the distance matrix is by far the largest input
    int xi = 0;
    for (int i = 1; i < n_in; i++)
        if (in_sizes[i] > in_sizes[xi]) xi = i;

    const float* x = (const float*)d_in[xi];
    float* out = (float*)d_out;

    const int rows = out_size / K_NEIGH;            // B * N  (= 65536 expected)
    const int N    = in_sizes[xi] / rows;           // num points (= 4096 expected)

    const int blocks = (rows + WPB - 1) / WPB;
    knn_thres_kernel<<<blocks, WPB * 32>>>(x, out, N, rows);
}